// round 17
// baseline (speedup 1.0000x reference)
#include <cuda_runtime.h>
#include <cuda_fp16.h>

#define STR 132            // smem row stride (floats): mult of 4 (16B align), conflict-free LDS.128
#define THREADS 512

typedef unsigned long long ull;

__device__ __forceinline__ void fma2(ull &acc, ull a, ull b) {
    asm("fma.rn.f32x2 %0, %1, %2, %0;" : "+l"(acc) : "l"(a), "l"(b));
}
__device__ __forceinline__ float2 unpack2(ull v) {
    unsigned int lo, hi;
    asm("mov.b64 {%0, %1}, %2;" : "=r"(lo), "=r"(hi) : "l"(v));
    return make_float2(__uint_as_float(lo), __uint_as_float(hi));
}

// Lloyd-Max bucketize (matches jnp.searchsorted side='left' over interior boundaries sB[1..15])
__device__ __forceinline__ float quantize1(float v, const float* __restrict__ sB,
                                           const float* __restrict__ sC) {
    int i = (v > sB[8]) ? 8 : 0;
    i += (v > sB[i + 4]) ? 4 : 0;
    i += (v > sB[i + 2]) ? 2 : 0;
    i += (v > sB[i + 1]) ? 1 : 0;
    return sC[i];
}

__global__ __launch_bounds__(THREADS, 1)
void tq_kernel(const float* __restrict__ x, const float* __restrict__ Pi,
               const float* __restrict__ cen, const float* __restrict__ bnd,
               float* __restrict__ out, int n_tiles)
{
    extern __shared__ float sm[];
    float* sPi  = sm;                  // [128][STR] Pi[j][k]   (b for GEMM1)
    float* sPiT = sPi  + 128 * STR;    // [128][STR] PiT[k][j]  (b for GEMM2)
    float* sX   = sPiT + 128 * STR;    // [128][STR] x tile / values tile (warp-private rows)
    float* sRn  = sX   + 128 * STR;    // [128]
    float* sNq  = sRn  + 128;          // [128]
    float* sB   = sNq  + 128;          // [16]
    float* sC   = sB   + 16;           // [16]

    const int tid  = threadIdx.x;
    const int w    = tid >> 5;         // warp 0..15 owns rows w*8..w*8+7 end-to-end
    const int lane = tid & 31;
    const int r0   = w * 8;

    // ---- stage Pi + PiT once per block ----
    #pragma unroll
    for (int it = 0; it < 8; ++it) {
        int idx = it * THREADS + tid;  // 4096 float4 reads
        int r = idx >> 5, c4 = (idx & 31) * 4;
        float4 v = reinterpret_cast<const float4*>(Pi)[idx];
        *reinterpret_cast<float4*>(&sPi[r * STR + c4]) = v;
        sPiT[(c4 + 0) * STR + r] = v.x;
        sPiT[(c4 + 1) * STR + r] = v.y;
        sPiT[(c4 + 2) * STR + r] = v.z;
        sPiT[(c4 + 3) * STR + r] = v.w;
    }
    if (tid < 16) sC[tid] = cen[tid];
    if (tid < 16) sB[tid] = bnd[tid];
    __syncthreads();

    for (int tile = blockIdx.x; tile < n_tiles; tile += gridDim.x) {
        const float* gx   = x   + (size_t)tile * 128 * 128;
        float*       gout = out + (size_t)tile * 128 * 128;

        // ---- stage own 8 rows + norms (warp-exclusive; no block syncs in loop) ----
        #pragma unroll
        for (int i = 0; i < 8; ++i) {
            int r = r0 + i;
            float4 v = *reinterpret_cast<const float4*>(gx + r * 128 + lane * 4);
            *reinterpret_cast<float4*>(&sX[r * STR + lane * 4]) = v;
            float s = v.x * v.x + v.y * v.y + v.z * v.z + v.w * v.w;
            s += __shfl_xor_sync(0xffffffffu, s, 16);
            s += __shfl_xor_sync(0xffffffffu, s, 8);
            s += __shfl_xor_sync(0xffffffffu, s, 4);
            s += __shfl_xor_sync(0xffffffffu, s, 2);
            s += __shfl_xor_sync(0xffffffffu, s, 1);
            if (lane == 0) {
                float nrm = sqrtf(s);
                sRn[r] = 1.0f / (nrm + 1e-8f);
                sNq[r] = __half2float(__float2half_rn(nrm));
            }
        }
        __syncwarp();

        // ---- GEMM 1: rot[r][j] = sum_k x[r][k] * Pi[j][k]
        //      ulonglong2 16B loads: a = x k-quad (broadcast), b = Pi[j] k-quad (lane j)
        //      acc[i][g] = (even-k sum, odd-k sum) for j = lane + 32g ----
        ull acc[8][4];
        #pragma unroll
        for (int i = 0; i < 8; ++i)
            #pragma unroll
            for (int g = 0; g < 4; ++g) acc[i][g] = 0ull;

        {
            const float* aP = sX  + r0 * STR;
            const float* bP = sPi + lane * STR;
            #pragma unroll 8
            for (int kb = 0; kb < 32; ++kb) {          // 4 k per kb
                ulonglong2 b0 = *reinterpret_cast<const ulonglong2*>(bP + 4 * kb);
                ulonglong2 b1 = *reinterpret_cast<const ulonglong2*>(bP + 32 * STR + 4 * kb);
                ulonglong2 b2 = *reinterpret_cast<const ulonglong2*>(bP + 64 * STR + 4 * kb);
                ulonglong2 b3 = *reinterpret_cast<const ulonglong2*>(bP + 96 * STR + 4 * kb);
                #pragma unroll
                for (int i = 0; i < 8; ++i) {
                    ulonglong2 a = *reinterpret_cast<const ulonglong2*>(aP + i * STR + 4 * kb);
                    fma2(acc[i][0], a.x, b0.x); fma2(acc[i][0], a.y, b0.y);
                    fma2(acc[i][1], a.x, b1.x); fma2(acc[i][1], a.y, b1.y);
                    fma2(acc[i][2], a.x, b2.x); fma2(acc[i][2], a.y, b2.y);
                    fma2(acc[i][3], a.x, b3.x); fma2(acc[i][3], a.y, b3.y);
                }
            }
        }
        __syncwarp();

        // ---- quantize own rows -> values tile (in place) ----
        #pragma unroll
        for (int i = 0; i < 8; ++i) {
            int r = r0 + i;
            float rn = sRn[r];
            #pragma unroll
            for (int g = 0; g < 4; ++g) {
                float2 p = unpack2(acc[i][g]);
                float v = (p.x + p.y) * rn;
                sX[r * STR + lane + 32 * g] = quantize1(v, sB, sC);
            }
        }
        __syncwarp();

        // ---- GEMM 2: recon[r][k] = sum_j values[r][j] * Pi[j][k]
        //      a = values j-quad (broadcast), b = PiT[k] j-quad (lane k = lane + 32g) ----
        #pragma unroll
        for (int i = 0; i < 8; ++i)
            #pragma unroll
            for (int g = 0; g < 4; ++g) acc[i][g] = 0ull;

        {
            const float* aP = sX   + r0 * STR;
            const float* bP = sPiT + lane * STR;
            #pragma unroll 8
            for (int jb = 0; jb < 32; ++jb) {          // 4 j per jb
                ulonglong2 b0 = *reinterpret_cast<const ulonglong2*>(bP + 4 * jb);
                ulonglong2 b1 = *reinterpret_cast<const ulonglong2*>(bP + 32 * STR + 4 * jb);
                ulonglong2 b2 = *reinterpret_cast<const ulonglong2*>(bP + 64 * STR + 4 * jb);
                ulonglong2 b3 = *reinterpret_cast<const ulonglong2*>(bP + 96 * STR + 4 * jb);
                #pragma unroll
                for (int i = 0; i < 8; ++i) {
                    ulonglong2 a = *reinterpret_cast<const ulonglong2*>(aP + i * STR + 4 * jb);
                    fma2(acc[i][0], a.x, b0.x); fma2(acc[i][0], a.y, b0.y);
                    fma2(acc[i][1], a.x, b1.x); fma2(acc[i][1], a.y, b1.y);
                    fma2(acc[i][2], a.x, b2.x); fma2(acc[i][2], a.y, b2.y);
                    fma2(acc[i][3], a.x, b3.x); fma2(acc[i][3], a.y, b3.y);
                }
            }
        }

        // ---- scale by fp16-roundtripped norm, store (coalesced STG.32) ----
        #pragma unroll
        for (int i = 0; i < 8; ++i) {
            int r = r0 + i;
            float nq = sNq[r];
            #pragma unroll
            for (int g = 0; g < 4; ++g) {
                float2 p = unpack2(acc[i][g]);
                gout[r * 128 + lane + 32 * g] = (p.x + p.y) * nq;
            }
        }
        __syncwarp();   // own-row sX reads done before next tile's staging overwrites
    }
}

extern "C" void kernel_launch(void* const* d_in, const int* in_sizes, int n_in,
                              void* d_out, int out_size) {
    const float* x   = (const float*)d_in[0];
    const float* Pi  = (const float*)d_in[1];
    const float* cen = (const float*)d_in[2];
    const float* bnd = (const float*)d_in[3];
    float* out = (float*)d_out;

    int n_rows  = in_sizes[0] / 128;
    int n_tiles = n_rows / 128;

    int nsm = 148;
    cudaDeviceGetAttribute(&nsm, cudaDevAttrMultiProcessorCount, 0);
    if (nsm <= 0) nsm = 148;

    size_t smem_bytes = (size_t)(3 * 128 * STR + 128 + 128 + 16 + 16) * sizeof(float);
    cudaFuncSetAttribute(tq_kernel, cudaFuncAttributeMaxDynamicSharedMemorySize, (int)smem_bytes);

    tq_kernel<<<nsm, THREADS, smem_bytes>>>(x, Pi, cen, bnd, out, n_tiles);
}